// round 11
// baseline (speedup 1.0000x reference)
#include <cuda_runtime.h>
#include <cuda_fp16.h>
#include <cstdint>
#include <cstddef>

// problem constants
#define NIN   1152
#define NOUT  10
#define DIN   8
#define DOUT  16
#define BB    256
#define JO    160
#define KD    9216
#define IJ    11520
#define KSPLIT 32
#define KCHUNK 288

// Row index convention for the contraction dim: r = i*8 + d  (capsule-major).
__device__ __half g_xh[(size_t)BB * KD];      // [b][r]
__device__ __half g_xt[(size_t)KD * BB];      // [r][b]
__device__ __half g_wt[(size_t)KD * JO];      // [r][jo]  unscaled W
__device__ __half g_wc[(size_t)KD * JO];      // [r][jo]  c-scaled W (per iter)
__device__ __half g_vh[BB * JO];              // [b][jo]
__device__ float  g_s[BB * JO];               // s accumulator (RED target)
__device__ float  g_blog[IJ];

__device__ __forceinline__ unsigned int smem_u32(const void* p) {
    return (unsigned int)__cvta_generic_to_shared(p);
}

__device__ __forceinline__ void ldsm_x4(unsigned int& r0, unsigned int& r1,
                                        unsigned int& r2, unsigned int& r3,
                                        unsigned int addr) {
    asm volatile("ldmatrix.sync.aligned.m8n8.x4.shared.b16 {%0,%1,%2,%3}, [%4];"
                 : "=r"(r0), "=r"(r1), "=r"(r2), "=r"(r3) : "r"(addr));
}

__device__ __forceinline__ void ldsm_x2t(unsigned int& r0, unsigned int& r1,
                                         unsigned int addr) {
    asm volatile("ldmatrix.sync.aligned.m8n8.x2.trans.shared.b16 {%0,%1}, [%2];"
                 : "=r"(r0), "=r"(r1) : "r"(addr));
}

__device__ __forceinline__ void mma16816(float* c,
                                         unsigned int a0, unsigned int a1,
                                         unsigned int a2, unsigned int a3,
                                         unsigned int b0, unsigned int b1) {
    asm volatile(
        "mma.sync.aligned.m16n8k16.row.col.f32.f16.f16.f32 "
        "{%0,%1,%2,%3}, {%4,%5,%6,%7}, {%8,%9}, {%0,%1,%2,%3};"
        : "+f"(c[0]), "+f"(c[1]), "+f"(c[2]), "+f"(c[3])
        : "r"(a0), "r"(a1), "r"(a2), "r"(a3), "r"(b0), "r"(b1));
}

// prep (fused): blocks [0,2304): x transpose/convert 32x32 tiles
//               blocks [2304,3456): W convert + Wc=0.1W + blog init
// blocks [0,160) additionally zero g_s.
__global__ __launch_bounds__(256) void k_prep(const float* __restrict__ x,
                                              const float* __restrict__ w) {
    const int t = threadIdx.x;
    if (blockIdx.x < 2304) {
        __shared__ float tile[32][33];
        const int tl = blockIdx.x;
        const int txi = tl % 288;
        const int tyb = tl / 288;
        const int di0 = txi * 32;
        const int b0 = tyb * 32;
        const int d = di0 / NIN;
        const int ibase = di0 - d * NIN;
        const int tx = t & 31;
        const int ty = t >> 5;
        #pragma unroll
        for (int q = 0; q < 4; q++) {
            int r = ty + q * 8;
            float v = x[(size_t)(b0 + r) * KD + di0 + tx];
            tile[r][tx] = v;
            g_xh[(size_t)(b0 + r) * KD + (ibase + tx) * 8 + d] = __float2half(v);
        }
        __syncthreads();
        #pragma unroll
        for (int q = 0; q < 4; q++) {
            int r = ty + q * 8;
            g_xt[(size_t)((ibase + r) * 8 + d) * BB + b0 + tx] =
                __float2half(tile[tx][r]);
        }
        if (blockIdx.x < 160) g_s[blockIdx.x * 256 + t] = 0.f;
    } else {
        __shared__ float sh[1280];
        const int i = blockIdx.x - 2304;
        #pragma unroll
        for (int q = 0; q < 5; q++) {
            sh[t + q * 256] = w[(size_t)i * 1280 + t + q * 256];
        }
        __syncthreads();
        if (t < 160) {
            #pragma unroll
            for (int d = 0; d < 8; d++) {
                float raw = sh[(t >> 4) * 128 + (t & 15) * 8 + d];
                g_wt[(size_t)(i * 8 + d) * JO + t] = __float2half(raw);
                g_wc[(size_t)(i * 8 + d) * JO + t] = __float2half(0.1f * raw);
            }
            if (t < 10) g_blog[i * 10 + t] = 0.f;
        }
    }
}

// GEMM s: g_s[b][jo] += sum_k xh[b][k] * Wc[k][jo] over this split's K-chunk.
// 256 threads (8 warps), tile 64 b x 160 jo, 18 k-steps of 16.
// Register prefetch: next k-step's global loads issue between the two
// syncs so LDG latency overlaps the ldsm+mma bundle.
__global__ __launch_bounds__(256) void k_gemm_s() {
    __shared__ __align__(16) __half As[64 * 24];
    __shared__ __align__(16) __half Bs[16 * 168];
    const int t = threadIdx.x;
    const int lane = t & 31;
    const int w = t >> 5;
    const int wr = w & 3;
    const int wc = w >> 2;
    const int split = blockIdx.x;
    const int m0 = blockIdx.y * 64;
    const int kbase = split * KCHUNK;

    float acc[10][4];
    #pragma unroll
    for (int n = 0; n < 10; n++) {
        #pragma unroll
        for (int q = 0; q < 4; q++) acc[n][q] = 0.f;
    }

    const unsigned int aaddr = smem_u32(As) +
        (unsigned int)(((wr * 16 + (lane & 15)) * 24 + (lane >> 4) * 8) * 2);
    const unsigned int baddr = smem_u32(Bs) +
        (unsigned int)(((lane & 15) * 168) * 2);

    const int ar0 = t >> 3;
    const int ac0 = (t & 7) * 2;
    const int be0 = t;
    uint32_t pa[2];
    uint2 pb[3];

    {
        const int k0 = kbase;
        pa[0] = *(const uint32_t*)(g_xh + (size_t)(m0 + ar0) * KD + k0 + ac0);
        pa[1] = *(const uint32_t*)(g_xh + (size_t)(m0 + ar0 + 32) * KD + k0 + ac0);
        #pragma unroll
        for (int q = 0; q < 3; q++) {
            int e = be0 + q * 256;
            if (e < 640) {
                int r = e / 40;
                int c8 = e - r * 40;
                pb[q] = *(const uint2*)(g_wc + (size_t)(k0 + r) * JO + c8 * 4);
            }
        }
    }

    for (int kk = 0; kk < 18; kk++) {
        *(uint32_t*)(As + ar0 * 24 + ac0) = pa[0];
        *(uint32_t*)(As + (ar0 + 32) * 24 + ac0) = pa[1];
        #pragma unroll
        for (int q = 0; q < 3; q++) {
            int e = be0 + q * 256;
            if (e < 640) {
                int r = e / 40;
                int c8 = e - r * 40;
                *(uint2*)(Bs + r * 168 + c8 * 4) = pb[q];
            }
        }
        __syncthreads();
        if (kk < 17) {
            const int k0 = kbase + (kk + 1) * 16;
            pa[0] = *(const uint32_t*)(g_xh + (size_t)(m0 + ar0) * KD + k0 + ac0);
            pa[1] = *(const uint32_t*)(g_xh + (size_t)(m0 + ar0 + 32) * KD + k0 + ac0);
            #pragma unroll
            for (int q = 0; q < 3; q++) {
                int e = be0 + q * 256;
                if (e < 640) {
                    int r = e / 40;
                    int c8 = e - r * 40;
                    pb[q] = *(const uint2*)(g_wc + (size_t)(k0 + r) * JO + c8 * 4);
                }
            }
        }
        unsigned int a0, a1, a2, a3;
        ldsm_x4(a0, a1, a2, a3, aaddr);
        #pragma unroll
        for (int nt = 0; nt < 10; nt++) {
            unsigned int b0, b1;
            ldsm_x2t(b0, b1, baddr + (unsigned int)((wc * 80 + nt * 8) * 2));
            mma16816(acc[nt], a0, a1, a2, a3, b0, b1);
        }
        __syncthreads();
    }
    const int g = lane >> 2;
    const int c2 = (lane & 3) * 2;
    float* base = g_s + (size_t)m0 * JO;
    #pragma unroll
    for (int nt = 0; nt < 10; nt++) {
        int col = wc * 80 + nt * 8 + c2;
        int row = wr * 16 + g;
        atomicAdd(base + (size_t)row * JO + col,           acc[nt][0]);
        atomicAdd(base + (size_t)row * JO + col + 1,       acc[nt][1]);
        atomicAdd(base + (size_t)(row + 8) * JO + col,     acc[nt][2]);
        atomicAdd(base + (size_t)(row + 8) * JO + col + 1, acc[nt][3]);
    }
}

// squash: v = squash(g_s); store fp16 v (+ fp32 out on last iter);
// zero g_s for the next iteration's accumulation.
__global__ __launch_bounds__(160) void k_squash(float* __restrict__ outp) {
    __shared__ float sh[JO];
    const int b = blockIdx.x;
    const int t = threadIdx.x;
    float s = g_s[b * JO + t];
    sh[t] = s * s;
    __syncthreads();
    const int base = (t >> 4) << 4;
    float sq = 0.f;
    #pragma unroll
    for (int o = 0; o < 16; o++) sq += sh[base + o];
    float fac = (sq / (1.f + sq)) * rsqrtf(sq + 1e-9f);
    float v = s * fac;
    g_vh[b * JO + t] = __float2half(v);
    if (outp) outp[b * JO + t] = v;
    g_s[b * JO + t] = 0.f;
}

// GEMM M + route fused: M[r][jo] = sum_b xt[r][b] * vh[b][jo]; then
// a[i][j] = sum_{d,o} Wt[r][jo] * M[r][jo] for the 4 capsules in this block;
// blog += a/256; c = softmax_j(blog) in smem; write Wc = c*Wt.
// 256 threads (8 warps: wr = row half, wc = 40-col quarter), 32 rows/block,
// 288 blocks (2 CTAs/SM), register prefetch on the k-loop.
__global__ __launch_bounds__(256) void k_gemm_mr() {
    __shared__ __align__(16) __half As[32 * 24];
    __shared__ __align__(16) __half Bs[16 * 168];
    __shared__ float sa[40];               // agreement [cap 0..3][j 0..9]
    __shared__ float sc[40];               // softmax   [cap 0..3][j 0..9]
    const int t = threadIdx.x;
    const int lane = t & 31;
    const int w = t >> 5;
    const int wr = w & 1;                  // row half (16 rows)
    const int wc = w >> 1;                 // 40-col quarter
    const int m0 = blockIdx.x * 32;
    const int i0 = m0 >> 3;                // 4 caps per block

    if (t < 40) sa[t] = 0.f;

    float acc[5][4];
    #pragma unroll
    for (int n = 0; n < 5; n++) {
        #pragma unroll
        for (int q = 0; q < 4; q++) acc[n][q] = 0.f;
    }

    const unsigned int aaddr = smem_u32(As) +
        (unsigned int)(((wr * 16 + (lane & 15)) * 24 + (lane >> 4) * 8) * 2);
    const unsigned int baddr = smem_u32(Bs) +
        (unsigned int)(((lane & 15) * 168) * 2);

    // per-thread staging: A = 32 rows x 16 halves = 256 u32 (1/thread)
    const int ar0 = t >> 3;                // 0..31
    const int ac0 = (t & 7) * 2;
    const int be0 = t;
    uint32_t pa;
    uint2 pb[3];

    {
        pa = *(const uint32_t*)(g_xt + (size_t)(m0 + ar0) * BB + ac0);
        #pragma unroll
        for (int q = 0; q < 3; q++) {
            int e = be0 + q * 256;
            if (e < 640) {
                int r = e / 40;
                int c8 = e - r * 40;
                pb[q] = *(const uint2*)(g_vh + (size_t)r * JO + c8 * 4);
            }
        }
    }

    for (int kk = 0; kk < 16; kk++) {
        *(uint32_t*)(As + ar0 * 24 + ac0) = pa;
        #pragma unroll
        for (int q = 0; q < 3; q++) {
            int e = be0 + q * 256;
            if (e < 640) {
                int r = e / 40;
                int c8 = e - r * 40;
                *(uint2*)(Bs + r * 168 + c8 * 4) = pb[q];
            }
        }
        __syncthreads();
        if (kk < 15) {
            const int k0 = (kk + 1) * 16;
            pa = *(const uint32_t*)(g_xt + (size_t)(m0 + ar0) * BB + k0 + ac0);
            #pragma unroll
            for (int q = 0; q < 3; q++) {
                int e = be0 + q * 256;
                if (e < 640) {
                    int r = e / 40;
                    int c8 = e - r * 40;
                    pb[q] = *(const uint2*)(g_vh + (size_t)(k0 + r) * JO + c8 * 4);
                }
            }
        }
        unsigned int a0, a1, a2, a3;
        ldsm_x4(a0, a1, a2, a3, aaddr);
        #pragma unroll
        for (int nt = 0; nt < 5; nt++) {
            unsigned int b0, b1;
            ldsm_x2t(b0, b1, baddr + (unsigned int)((wc * 40 + nt * 8) * 2));
            mma16816(acc[nt], a0, a1, a2, a3, b0, b1);
        }
        __syncthreads();
    }

    // route epilogue: warp (wr,wc) holds rows r1 = m0+wr*16+g (cap wr*2) and
    // r1+8 (cap wr*2+1), cols wc*40+nt*8+c2 -> j = (wc*5+nt)>>1.
    const int g = lane >> 2;
    const int c2 = (lane & 3) * 2;
    const int r1 = m0 + wr * 16 + g;
    const int r2 = r1 + 8;
    float p0[5];
    float p1[5];
    #pragma unroll
    for (int n = 0; n < 5; n++) { p0[n] = 0.f; p1[n] = 0.f; }
    #pragma unroll
    for (int nt = 0; nt < 5; nt++) {
        int col = wc * 40 + nt * 8 + c2;
        __half2 w1 = *(const __half2*)(g_wt + (size_t)r1 * JO + col);
        __half2 w2 = *(const __half2*)(g_wt + (size_t)r2 * JO + col);
        float2 f1 = __half22float2(w1);
        float2 f2 = __half22float2(w2);
        p0[nt] += acc[nt][0] * f1.x + acc[nt][1] * f1.y;
        p1[nt] += acc[nt][2] * f2.x + acc[nt][3] * f2.y;
    }
    #pragma unroll
    for (int n = 0; n < 5; n++) {
        #pragma unroll
        for (int off = 16; off > 0; off >>= 1) {
            p0[n] += __shfl_xor_sync(0xffffffffu, p0[n], off);
            p1[n] += __shfl_xor_sync(0xffffffffu, p1[n], off);
        }
    }
    if (lane == 0) {
        #pragma unroll
        for (int n = 0; n < 5; n++) {
            int j = (wc * 5 + n) >> 1;
            atomicAdd(&sa[(wr * 2) * 10 + j], p0[n]);
            atomicAdd(&sa[(wr * 2 + 1) * 10 + j], p1[n]);
        }
    }
    __syncthreads();
    if (t < 4) {
        const int i = i0 + t;
        float bl[10];
        float ex[10];
        float mx = -1e30f;
        #pragma unroll
        for (int j = 0; j < 10; j++) {
            float nb = g_blog[i * 10 + j] + sa[t * 10 + j] * (1.0f / 256.0f);
            g_blog[i * 10 + j] = nb;
            bl[j] = nb;
            mx = fmaxf(mx, nb);
        }
        float sum = 0.f;
        #pragma unroll
        for (int j = 0; j < 10; j++) {
            ex[j] = expf(bl[j] - mx);
            sum += ex[j];
        }
        float inv = 1.f / sum;
        #pragma unroll
        for (int j = 0; j < 10; j++) {
            sc[t * 10 + j] = ex[j] * inv;
        }
    }
    __syncthreads();

    // write Wc = c * Wt for this block's 32 rows (next iteration's B).
    #pragma unroll
    for (int q = 0; q < 5; q++) {              // 32 rows x 40 uint2 = 1280
        int e = t + q * 256;
        int r = e / 40;
        int c8 = e - r * 40;
        int j = c8 >> 2;
        float cw = sc[(r >> 3) * 10 + j];
        uint2 raw = *(const uint2*)(g_wt + (size_t)(m0 + r) * JO + c8 * 4);
        __half2 h0 = *(__half2*)&raw.x;
        __half2 h1 = *(__half2*)&raw.y;
        float2 f0 = __half22float2(h0);
        float2 f1 = __half22float2(h1);
        __half2 o0 = __floats2half2_rn(cw * f0.x, cw * f0.y);
        __half2 o1 = __floats2half2_rn(cw * f1.x, cw * f1.y);
        uint2 outv;
        outv.x = *(unsigned int*)&o0;
        outv.y = *(unsigned int*)&o1;
        *(uint2*)(g_wc + (size_t)(m0 + r) * JO + c8 * 4) = outv;
    }
}

extern "C" void kernel_launch(void* const* d_in, const int* in_sizes, int n_in,
                              void* d_out, int out_size) {
    const float* x = (const float*)d_in[0];
    const float* w = (const float*)d_in[1];
    if (n_in >= 2 && in_sizes[0] == NIN * NOUT * DOUT * DIN
                  && in_sizes[1] == BB * DIN * NIN) {
        const float* tmp = x;
        x = w;
        w = tmp;
    }
    float* out = (float*)d_out;

    k_prep<<<3456, 256>>>(x, w);

    k_gemm_s<<<dim3(KSPLIT, 4), 256>>>();
    k_squash<<<BB, 160>>>((float*)0);
    k_gemm_mr<<<KD / 32, 256>>>();

    k_gemm_s<<<dim3(KSPLIT, 4), 256>>>();
    k_squash<<<BB, 160>>>((float*)0);
    k_gemm_mr<<<KD / 32, 256>>>();

    k_gemm_s<<<dim3(KSPLIT, 4), 256>>>();
    k_squash<<<BB, 160>>>(out);
}

// round 12
// speedup vs baseline: 1.0569x; 1.0569x over previous
#include <cuda_runtime.h>
#include <cuda_fp16.h>
#include <cstdint>
#include <cstddef>

// problem constants
#define NIN   1152
#define NOUT  10
#define DIN   8
#define DOUT  16
#define BB    256
#define JO    160
#define KD    9216
#define IJ    11520
#define KSPLIT 32
#define KCHUNK 288

// k_gemm_mr dynamic smem layout (bytes):
//   As: 64 rows x 264 halves = 33792
//   Bs: 256 rows x 168 halves = 86016
//   sa: 80 floats = 320; sc: 80 floats = 320
#define MR_AS_BYTES   33792
#define MR_BS_BYTES   86016
#define MR_SMEM_BYTES (MR_AS_BYTES + MR_BS_BYTES + 640)

// Row index convention for the contraction dim: r = i*8 + d  (capsule-major).
__device__ __half g_xh[(size_t)BB * KD];      // [b][r]
__device__ __half g_xt[(size_t)KD * BB];      // [r][b]
__device__ __half g_wt[(size_t)KD * JO];      // [r][jo]  unscaled W
__device__ __half g_wc[(size_t)KD * JO];      // [r][jo]  c-scaled W (per iter)
__device__ __half g_vh[BB * JO];              // [b][jo]
__device__ float  g_s[BB * JO];               // s accumulator (RED target)
__device__ float  g_blog[IJ];

__device__ __forceinline__ unsigned int smem_u32(const void* p) {
    return (unsigned int)__cvta_generic_to_shared(p);
}

__device__ __forceinline__ void ldsm_x4(unsigned int& r0, unsigned int& r1,
                                        unsigned int& r2, unsigned int& r3,
                                        unsigned int addr) {
    asm volatile("ldmatrix.sync.aligned.m8n8.x4.shared.b16 {%0,%1,%2,%3}, [%4];"
                 : "=r"(r0), "=r"(r1), "=r"(r2), "=r"(r3) : "r"(addr));
}

__device__ __forceinline__ void ldsm_x2t(unsigned int& r0, unsigned int& r1,
                                         unsigned int addr) {
    asm volatile("ldmatrix.sync.aligned.m8n8.x2.trans.shared.b16 {%0,%1}, [%2];"
                 : "=r"(r0), "=r"(r1) : "r"(addr));
}

__device__ __forceinline__ void mma16816(float* c,
                                         unsigned int a0, unsigned int a1,
                                         unsigned int a2, unsigned int a3,
                                         unsigned int b0, unsigned int b1) {
    asm volatile(
        "mma.sync.aligned.m16n8k16.row.col.f32.f16.f16.f32 "
        "{%0,%1,%2,%3}, {%4,%5,%6,%7}, {%8,%9}, {%0,%1,%2,%3};"
        : "+f"(c[0]), "+f"(c[1]), "+f"(c[2]), "+f"(c[3])
        : "r"(a0), "r"(a1), "r"(a2), "r"(a3), "r"(b0), "r"(b1));
}

// prep (fused): blocks [0,2304): x transpose/convert 32x32 tiles
//               blocks [2304,3456): W convert + Wc=0.1W + blog init
// blocks [0,160) additionally zero g_s.
__global__ __launch_bounds__(256) void k_prep(const float* __restrict__ x,
                                              const float* __restrict__ w) {
    const int t = threadIdx.x;
    if (blockIdx.x < 2304) {
        __shared__ float tile[32][33];
        const int tl = blockIdx.x;
        const int txi = tl % 288;
        const int tyb = tl / 288;
        const int di0 = txi * 32;
        const int b0 = tyb * 32;
        const int d = di0 / NIN;
        const int ibase = di0 - d * NIN;
        const int tx = t & 31;
        const int ty = t >> 5;
        #pragma unroll
        for (int q = 0; q < 4; q++) {
            int r = ty + q * 8;
            float v = x[(size_t)(b0 + r) * KD + di0 + tx];
            tile[r][tx] = v;
            g_xh[(size_t)(b0 + r) * KD + (ibase + tx) * 8 + d] = __float2half(v);
        }
        __syncthreads();
        #pragma unroll
        for (int q = 0; q < 4; q++) {
            int r = ty + q * 8;
            g_xt[(size_t)((ibase + r) * 8 + d) * BB + b0 + tx] =
                __float2half(tile[tx][r]);
        }
        if (blockIdx.x < 160) g_s[blockIdx.x * 256 + t] = 0.f;
    } else {
        __shared__ float sh[1280];
        const int i = blockIdx.x - 2304;
        #pragma unroll
        for (int q = 0; q < 5; q++) {
            sh[t + q * 256] = w[(size_t)i * 1280 + t + q * 256];
        }
        __syncthreads();
        if (t < 160) {
            #pragma unroll
            for (int d = 0; d < 8; d++) {
                float raw = sh[(t >> 4) * 128 + (t & 15) * 8 + d];
                g_wt[(size_t)(i * 8 + d) * JO + t] = __float2half(raw);
                g_wc[(size_t)(i * 8 + d) * JO + t] = __float2half(0.1f * raw);
            }
            if (t < 10) g_blog[i * 10 + t] = 0.f;
        }
    }
}

// GEMM s: g_s[b][jo] += sum_k xh[b][k] * Wc[k][jo] over this split's K-chunk.
// 256 threads (8 warps), tile 64 b x 160 jo, 18 k-steps of 16.
// Register prefetch: next k-step's global loads issue between the two
// syncs so LDG latency overlaps the ldsm+mma bundle.
__global__ __launch_bounds__(256) void k_gemm_s() {
    __shared__ __align__(16) __half As[64 * 24];
    __shared__ __align__(16) __half Bs[16 * 168];
    const int t = threadIdx.x;
    const int lane = t & 31;
    const int w = t >> 5;
    const int wr = w & 3;
    const int wc = w >> 2;
    const int split = blockIdx.x;
    const int m0 = blockIdx.y * 64;
    const int kbase = split * KCHUNK;

    float acc[10][4];
    #pragma unroll
    for (int n = 0; n < 10; n++) {
        #pragma unroll
        for (int q = 0; q < 4; q++) acc[n][q] = 0.f;
    }

    const unsigned int aaddr = smem_u32(As) +
        (unsigned int)(((wr * 16 + (lane & 15)) * 24 + (lane >> 4) * 8) * 2);
    const unsigned int baddr = smem_u32(Bs) +
        (unsigned int)(((lane & 15) * 168) * 2);

    const int ar0 = t >> 3;
    const int ac0 = (t & 7) * 2;
    const int be0 = t;
    uint32_t pa[2];
    uint2 pb[3];

    {
        const int k0 = kbase;
        pa[0] = *(const uint32_t*)(g_xh + (size_t)(m0 + ar0) * KD + k0 + ac0);
        pa[1] = *(const uint32_t*)(g_xh + (size_t)(m0 + ar0 + 32) * KD + k0 + ac0);
        #pragma unroll
        for (int q = 0; q < 3; q++) {
            int e = be0 + q * 256;
            if (e < 640) {
                int r = e / 40;
                int c8 = e - r * 40;
                pb[q] = *(const uint2*)(g_wc + (size_t)(k0 + r) * JO + c8 * 4);
            }
        }
    }

    for (int kk = 0; kk < 18; kk++) {
        *(uint32_t*)(As + ar0 * 24 + ac0) = pa[0];
        *(uint32_t*)(As + (ar0 + 32) * 24 + ac0) = pa[1];
        #pragma unroll
        for (int q = 0; q < 3; q++) {
            int e = be0 + q * 256;
            if (e < 640) {
                int r = e / 40;
                int c8 = e - r * 40;
                *(uint2*)(Bs + r * 168 + c8 * 4) = pb[q];
            }
        }
        __syncthreads();
        if (kk < 17) {
            const int k0 = kbase + (kk + 1) * 16;
            pa[0] = *(const uint32_t*)(g_xh + (size_t)(m0 + ar0) * KD + k0 + ac0);
            pa[1] = *(const uint32_t*)(g_xh + (size_t)(m0 + ar0 + 32) * KD + k0 + ac0);
            #pragma unroll
            for (int q = 0; q < 3; q++) {
                int e = be0 + q * 256;
                if (e < 640) {
                    int r = e / 40;
                    int c8 = e - r * 40;
                    pb[q] = *(const uint2*)(g_wc + (size_t)(k0 + r) * JO + c8 * 4);
                }
            }
        }
        unsigned int a0, a1, a2, a3;
        ldsm_x4(a0, a1, a2, a3, aaddr);
        #pragma unroll
        for (int nt = 0; nt < 10; nt++) {
            unsigned int b0, b1;
            ldsm_x2t(b0, b1, baddr + (unsigned int)((wc * 80 + nt * 8) * 2));
            mma16816(acc[nt], a0, a1, a2, a3, b0, b1);
        }
        __syncthreads();
    }
    const int g = lane >> 2;
    const int c2 = (lane & 3) * 2;
    float* base = g_s + (size_t)m0 * JO;
    #pragma unroll
    for (int nt = 0; nt < 10; nt++) {
        int col = wc * 80 + nt * 8 + c2;
        int row = wr * 16 + g;
        atomicAdd(base + (size_t)row * JO + col,           acc[nt][0]);
        atomicAdd(base + (size_t)row * JO + col + 1,       acc[nt][1]);
        atomicAdd(base + (size_t)(row + 8) * JO + col,     acc[nt][2]);
        atomicAdd(base + (size_t)(row + 8) * JO + col + 1, acc[nt][3]);
    }
}

// squash: v = squash(g_s); store fp16 v (+ fp32 out on last iter);
// zero g_s for the next iteration's accumulation.
__global__ __launch_bounds__(160) void k_squash(float* __restrict__ outp) {
    __shared__ float sh[JO];
    const int b = blockIdx.x;
    const int t = threadIdx.x;
    float s = g_s[b * JO + t];
    sh[t] = s * s;
    __syncthreads();
    const int base = (t >> 4) << 4;
    float sq = 0.f;
    #pragma unroll
    for (int o = 0; o < 16; o++) sq += sh[base + o];
    float fac = (sq / (1.f + sq)) * rsqrtf(sq + 1e-9f);
    float v = s * fac;
    g_vh[b * JO + t] = __float2half(v);
    if (outp) outp[b * JO + t] = v;
    g_s[b * JO + t] = 0.f;
}

// GEMM M + route fused, barrier-free mainloop:
// All of A (64 rows x 256) and all of B (256 x 160 = vh) are loaded into
// dynamic smem up front; ONE __syncthreads; then 16 k-steps of pure
// ldsm+mma with no barriers. Epilogue: agreement dot with Wt, softmax,
// Wc = c*Wt. 144 blocks x 256 threads (8 warps: wr row quarter, wc col half).
__global__ __launch_bounds__(256) void k_gemm_mr() {
    extern __shared__ __align__(16) unsigned char dyn[];
    __half* As = (__half*)dyn;                       // [64][264]
    __half* Bs = (__half*)(dyn + MR_AS_BYTES);       // [256][168]
    float*  sa = (float*)(dyn + MR_AS_BYTES + MR_BS_BYTES);        // [80]
    float*  sc = (float*)(dyn + MR_AS_BYTES + MR_BS_BYTES + 320);  // [80]

    const int t = threadIdx.x;
    const int lane = t & 31;
    const int w = t >> 5;
    const int wr = w & 3;                  // row quarter (16 rows)
    const int wc = w >> 2;                 // 80-col half
    const int m0 = blockIdx.x * 64;
    const int i0 = m0 >> 3;                // 8 caps per block

    // load A: 64 rows x 256 halves = 2048 uint4, 8 per thread
    #pragma unroll
    for (int q = 0; q < 8; q++) {
        int e = t + q * 256;
        int r = e >> 5;
        int c16 = (e & 31) * 8;
        *(uint4*)(As + r * 264 + c16) =
            *(const uint4*)(g_xt + (size_t)(m0 + r) * BB + c16);
    }
    // load B: 256 rows x 40 uint2 = 10240, 40 per thread
    #pragma unroll
    for (int q = 0; q < 40; q++) {
        int e = t + q * 256;
        int r = e / 40;
        int c8 = e - r * 40;
        *(uint2*)(Bs + r * 168 + c8 * 4) =
            *(const uint2*)(g_vh + (size_t)r * JO + c8 * 4);
    }
    __syncthreads();

    float acc[10][4];
    #pragma unroll
    for (int n = 0; n < 10; n++) {
        #pragma unroll
        for (int q = 0; q < 4; q++) acc[n][q] = 0.f;
    }

    const unsigned int aaddr = smem_u32(As) +
        (unsigned int)(((wr * 16 + (lane & 15)) * 264 + (lane >> 4) * 8) * 2);
    const unsigned int baddr = smem_u32(Bs) +
        (unsigned int)(((lane & 15) * 168) * 2);

    #pragma unroll
    for (int kk = 0; kk < 16; kk++) {
        unsigned int a0, a1, a2, a3;
        ldsm_x4(a0, a1, a2, a3, aaddr + (unsigned int)(kk * 32));
        const unsigned int bk = baddr + (unsigned int)(kk * 16 * 336);
        #pragma unroll
        for (int nt = 0; nt < 10; nt++) {
            unsigned int b0, b1;
            ldsm_x2t(b0, b1, bk + (unsigned int)((wc * 80 + nt * 8) * 2));
            mma16816(acc[nt], a0, a1, a2, a3, b0, b1);
        }
    }

    // route epilogue: warp (wr,wc) holds rows r1 = m0+wr*16+g (cap wr*2) and
    // r1+8 (cap wr*2+1), cols wc*80+nt*8+c2 -> j = wc*5 + nt/2.
    const int g = lane >> 2;
    const int c2 = (lane & 3) * 2;
    const int r1 = m0 + wr * 16 + g;
    const int r2 = r1 + 8;
    float p0[5];
    float p1[5];
    #pragma unroll
    for (int j = 0; j < 5; j++) { p0[j] = 0.f; p1[j] = 0.f; }
    #pragma unroll
    for (int nt = 0; nt < 10; nt++) {
        int col = wc * 80 + nt * 8 + c2;
        int jl = nt >> 1;
        __half2 w1 = *(const __half2*)(g_wt + (size_t)r1 * JO + col);
        __half2 w2 = *(const __half2*)(g_wt + (size_t)r2 * JO + col);
        float2 f1 = __half22float2(w1);
        float2 f2 = __half22float2(w2);
        p0[jl] += acc[nt][0] * f1.x + acc[nt][1] * f1.y;
        p1[jl] += acc[nt][2] * f2.x + acc[nt][3] * f2.y;
    }
    #pragma unroll
    for (int j = 0; j < 5; j++) {
        #pragma unroll
        for (int off = 16; off > 0; off >>= 1) {
            p0[j] += __shfl_xor_sync(0xffffffffu, p0[j], off);
            p1[j] += __shfl_xor_sync(0xffffffffu, p1[j], off);
        }
    }
    if (lane == 0) {
        #pragma unroll
        for (int j = 0; j < 5; j++) {
            sa[(wr * 2) * 10 + wc * 5 + j] = p0[j];
            sa[(wr * 2 + 1) * 10 + wc * 5 + j] = p1[j];
        }
    }
    __syncthreads();
    if (t < 8) {
        const int i = i0 + t;
        float bl[10];
        float ex[10];
        float mx = -1e30f;
        #pragma unroll
        for (int j = 0; j < 10; j++) {
            float nb = g_blog[i * 10 + j] + sa[t * 10 + j] * (1.0f / 256.0f);
            g_blog[i * 10 + j] = nb;
            bl[j] = nb;
            mx = fmaxf(mx, nb);
        }
        float sum = 0.f;
        #pragma unroll
        for (int j = 0; j < 10; j++) {
            ex[j] = expf(bl[j] - mx);
            sum += ex[j];
        }
        float inv = 1.f / sum;
        #pragma unroll
        for (int j = 0; j < 10; j++) {
            sc[t * 10 + j] = ex[j] * inv;
        }
    }
    __syncthreads();

    // write Wc = c * Wt for this block's 64 rows (next iteration's B).
    #pragma unroll
    for (int q = 0; q < 10; q++) {             // 64 rows x 40 uint2 = 2560
        int e = t + q * 256;
        int r = e / 40;
        int c8 = e - r * 40;
        int j = c8 >> 2;
        float cw = sc[(r >> 3) * 10 + j];
        uint2 raw = *(const uint2*)(g_wt + (size_t)(m0 + r) * JO + c8 * 4);
        __half2 h0 = *(__half2*)&raw.x;
        __half2 h1 = *(__half2*)&raw.y;
        float2 f0 = __half22float2(h0);
        float2 f1 = __half22float2(h1);
        __half2 o0 = __floats2half2_rn(cw * f0.x, cw * f0.y);
        __half2 o1 = __floats2half2_rn(cw * f1.x, cw * f1.y);
        uint2 outv;
        outv.x = *(unsigned int*)&o0;
        outv.y = *(unsigned int*)&o1;
        *(uint2*)(g_wc + (size_t)(m0 + r) * JO + c8 * 4) = outv;
    }
}

extern "C" void kernel_launch(void* const* d_in, const int* in_sizes, int n_in,
                              void* d_out, int out_size) {
    const float* x = (const float*)d_in[0];
    const float* w = (const float*)d_in[1];
    if (n_in >= 2 && in_sizes[0] == NIN * NOUT * DOUT * DIN
                  && in_sizes[1] == BB * DIN * NIN) {
        const float* tmp = x;
        x = w;
        w = tmp;
    }
    float* out = (float*)d_out;

    cudaFuncSetAttribute(k_gemm_mr,
                         cudaFuncAttributeMaxDynamicSharedMemorySize,
                         MR_SMEM_BYTES);

    k_prep<<<3456, 256>>>(x, w);

    k_gemm_s<<<dim3(KSPLIT, 4), 256>>>();
    k_squash<<<BB, 160>>>((float*)0);
    k_gemm_mr<<<KD / 64, 256, MR_SMEM_BYTES>>>();

    k_gemm_s<<<dim3(KSPLIT, 4), 256>>>();
    k_squash<<<BB, 160>>>((float*)0);
    k_gemm_mr<<<KD / 64, 256, MR_SMEM_BYTES>>>();

    k_gemm_s<<<dim3(KSPLIT, 4), 256>>>();
    k_squash<<<BB, 160>>>(out);
}

// round 13
// speedup vs baseline: 1.0620x; 1.0048x over previous
#include <cuda_runtime.h>
#include <cuda_fp16.h>
#include <cstdint>
#include <cstddef>

// problem constants
#define NIN   1152
#define NOUT  10
#define DIN   8
#define DOUT  16
#define BB    256
#define JO    160
#define KD    9216
#define IJ    11520
#define KSPLIT 32
#define KCHUNK 288

// k_gemm_mr dynamic smem layout (bytes):
//   As: 32 rows x 264 halves = 16896
//   Bs: 256 rows x 168 halves = 86016
//   sa: 40 floats = 160; sc: 40 floats = 160
#define MR_AS_BYTES   16896
#define MR_BS_BYTES   86016
#define MR_SMEM_BYTES (MR_AS_BYTES + MR_BS_BYTES + 320)

// Row index convention for the contraction dim: r = i*8 + d  (capsule-major).
__device__ __half g_xh[(size_t)BB * KD];      // [b][r]
__device__ __half g_xt[(size_t)KD * BB];      // [r][b]
__device__ __half g_wt[(size_t)KD * JO];      // [r][jo]  unscaled W
__device__ __half g_wc[(size_t)KD * JO];      // [r][jo]  c-scaled W (per iter)
__device__ __half g_vh[BB * JO];              // [b][jo]
__device__ float  g_s[BB * JO];               // s accumulator (RED target)
__device__ float  g_blog[IJ];

__device__ __forceinline__ unsigned int smem_u32(const void* p) {
    return (unsigned int)__cvta_generic_to_shared(p);
}

__device__ __forceinline__ void ldsm_x4(unsigned int& r0, unsigned int& r1,
                                        unsigned int& r2, unsigned int& r3,
                                        unsigned int addr) {
    asm volatile("ldmatrix.sync.aligned.m8n8.x4.shared.b16 {%0,%1,%2,%3}, [%4];"
                 : "=r"(r0), "=r"(r1), "=r"(r2), "=r"(r3) : "r"(addr));
}

__device__ __forceinline__ void ldsm_x2t(unsigned int& r0, unsigned int& r1,
                                         unsigned int addr) {
    asm volatile("ldmatrix.sync.aligned.m8n8.x2.trans.shared.b16 {%0,%1}, [%2];"
                 : "=r"(r0), "=r"(r1) : "r"(addr));
}

__device__ __forceinline__ void mma16816(float* c,
                                         unsigned int a0, unsigned int a1,
                                         unsigned int a2, unsigned int a3,
                                         unsigned int b0, unsigned int b1) {
    asm volatile(
        "mma.sync.aligned.m16n8k16.row.col.f32.f16.f16.f32 "
        "{%0,%1,%2,%3}, {%4,%5,%6,%7}, {%8,%9}, {%0,%1,%2,%3};"
        : "+f"(c[0]), "+f"(c[1]), "+f"(c[2]), "+f"(c[3])
        : "r"(a0), "r"(a1), "r"(a2), "r"(a3), "r"(b0), "r"(b1));
}

// prep (fused): blocks [0,2304): x transpose/convert 32x32 tiles
//               blocks [2304,3456): W convert + Wc=0.1W + blog init
// blocks [0,160) additionally zero g_s.
__global__ __launch_bounds__(256) void k_prep(const float* __restrict__ x,
                                              const float* __restrict__ w) {
    const int t = threadIdx.x;
    if (blockIdx.x < 2304) {
        __shared__ float tile[32][33];
        const int tl = blockIdx.x;
        const int txi = tl % 288;
        const int tyb = tl / 288;
        const int di0 = txi * 32;
        const int b0 = tyb * 32;
        const int d = di0 / NIN;
        const int ibase = di0 - d * NIN;
        const int tx = t & 31;
        const int ty = t >> 5;
        #pragma unroll
        for (int q = 0; q < 4; q++) {
            int r = ty + q * 8;
            float v = x[(size_t)(b0 + r) * KD + di0 + tx];
            tile[r][tx] = v;
            g_xh[(size_t)(b0 + r) * KD + (ibase + tx) * 8 + d] = __float2half(v);
        }
        __syncthreads();
        #pragma unroll
        for (int q = 0; q < 4; q++) {
            int r = ty + q * 8;
            g_xt[(size_t)((ibase + r) * 8 + d) * BB + b0 + tx] =
                __float2half(tile[tx][r]);
        }
        if (blockIdx.x < 160) g_s[blockIdx.x * 256 + t] = 0.f;
    } else {
        __shared__ float sh[1280];
        const int i = blockIdx.x - 2304;
        #pragma unroll
        for (int q = 0; q < 5; q++) {
            sh[t + q * 256] = w[(size_t)i * 1280 + t + q * 256];
        }
        __syncthreads();
        if (t < 160) {
            #pragma unroll
            for (int d = 0; d < 8; d++) {
                float raw = sh[(t >> 4) * 128 + (t & 15) * 8 + d];
                g_wt[(size_t)(i * 8 + d) * JO + t] = __float2half(raw);
                g_wc[(size_t)(i * 8 + d) * JO + t] = __float2half(0.1f * raw);
            }
            if (t < 10) g_blog[i * 10 + t] = 0.f;
        }
    }
}

// GEMM s: g_s[b][jo] += sum_k xh[b][k] * Wc[k][jo] over this split's K-chunk.
// 256 threads (8 warps), tile 64 b x 160 jo, 18 k-steps of 16.
// Register prefetch: next k-step's global loads issue between the two
// syncs so LDG latency overlaps the ldsm+mma bundle.
__global__ __launch_bounds__(256) void k_gemm_s() {
    __shared__ __align__(16) __half As[64 * 24];
    __shared__ __align__(16) __half Bs[16 * 168];
    const int t = threadIdx.x;
    const int lane = t & 31;
    const int w = t >> 5;
    const int wr = w & 3;
    const int wc = w >> 2;
    const int split = blockIdx.x;
    const int m0 = blockIdx.y * 64;
    const int kbase = split * KCHUNK;

    float acc[10][4];
    #pragma unroll
    for (int n = 0; n < 10; n++) {
        #pragma unroll
        for (int q = 0; q < 4; q++) acc[n][q] = 0.f;
    }

    const unsigned int aaddr = smem_u32(As) +
        (unsigned int)(((wr * 16 + (lane & 15)) * 24 + (lane >> 4) * 8) * 2);
    const unsigned int baddr = smem_u32(Bs) +
        (unsigned int)(((lane & 15) * 168) * 2);

    const int ar0 = t >> 3;
    const int ac0 = (t & 7) * 2;
    const int be0 = t;
    uint32_t pa[2];
    uint2 pb[3];

    {
        const int k0 = kbase;
        pa[0] = *(const uint32_t*)(g_xh + (size_t)(m0 + ar0) * KD + k0 + ac0);
        pa[1] = *(const uint32_t*)(g_xh + (size_t)(m0 + ar0 + 32) * KD + k0 + ac0);
        #pragma unroll
        for (int q = 0; q < 3; q++) {
            int e = be0 + q * 256;
            if (e < 640) {
                int r = e / 40;
                int c8 = e - r * 40;
                pb[q] = *(const uint2*)(g_wc + (size_t)(k0 + r) * JO + c8 * 4);
            }
        }
    }

    for (int kk = 0; kk < 18; kk++) {
        *(uint32_t*)(As + ar0 * 24 + ac0) = pa[0];
        *(uint32_t*)(As + (ar0 + 32) * 24 + ac0) = pa[1];
        #pragma unroll
        for (int q = 0; q < 3; q++) {
            int e = be0 + q * 256;
            if (e < 640) {
                int r = e / 40;
                int c8 = e - r * 40;
                *(uint2*)(Bs + r * 168 + c8 * 4) = pb[q];
            }
        }
        __syncthreads();
        if (kk < 17) {
            const int k0 = kbase + (kk + 1) * 16;
            pa[0] = *(const uint32_t*)(g_xh + (size_t)(m0 + ar0) * KD + k0 + ac0);
            pa[1] = *(const uint32_t*)(g_xh + (size_t)(m0 + ar0 + 32) * KD + k0 + ac0);
            #pragma unroll
            for (int q = 0; q < 3; q++) {
                int e = be0 + q * 256;
                if (e < 640) {
                    int r = e / 40;
                    int c8 = e - r * 40;
                    pb[q] = *(const uint2*)(g_wc + (size_t)(k0 + r) * JO + c8 * 4);
                }
            }
        }
        unsigned int a0, a1, a2, a3;
        ldsm_x4(a0, a1, a2, a3, aaddr);
        #pragma unroll
        for (int nt = 0; nt < 10; nt++) {
            unsigned int b0, b1;
            ldsm_x2t(b0, b1, baddr + (unsigned int)((wc * 80 + nt * 8) * 2));
            mma16816(acc[nt], a0, a1, a2, a3, b0, b1);
        }
        __syncthreads();
    }
    const int g = lane >> 2;
    const int c2 = (lane & 3) * 2;
    float* base = g_s + (size_t)m0 * JO;
    #pragma unroll
    for (int nt = 0; nt < 10; nt++) {
        int col = wc * 80 + nt * 8 + c2;
        int row = wr * 16 + g;
        atomicAdd(base + (size_t)row * JO + col,           acc[nt][0]);
        atomicAdd(base + (size_t)row * JO + col + 1,       acc[nt][1]);
        atomicAdd(base + (size_t)(row + 8) * JO + col,     acc[nt][2]);
        atomicAdd(base + (size_t)(row + 8) * JO + col + 1, acc[nt][3]);
    }
}

// squash: v = squash(g_s); store fp16 v (+ fp32 out on last iter);
// zero g_s for the next iteration's accumulation.
__global__ __launch_bounds__(160) void k_squash(float* __restrict__ outp) {
    __shared__ float sh[JO];
    const int b = blockIdx.x;
    const int t = threadIdx.x;
    float s = g_s[b * JO + t];
    sh[t] = s * s;
    __syncthreads();
    const int base = (t >> 4) << 4;
    float sq = 0.f;
    #pragma unroll
    for (int o = 0; o < 16; o++) sq += sh[base + o];
    float fac = (sq / (1.f + sq)) * rsqrtf(sq + 1e-9f);
    float v = s * fac;
    g_vh[b * JO + t] = __float2half(v);
    if (outp) outp[b * JO + t] = v;
    g_s[b * JO + t] = 0.f;
}

// GEMM M + route fused, barrier-free mainloop, 32 rows/block, 288 blocks,
// 2 CTAs/SM co-resident (smem 103.4 KB). All of A (32 x 256) and all of B
// (256 x 160 = vh) loaded up front; ONE __syncthreads; 16 k-steps of pure
// ldsm+mma. Epilogue: agreement dot with Wt, softmax, Wc = c*Wt.
// 8 warps: wr = row half (16 rows), wc = 40-col quarter.
__global__ __launch_bounds__(256) void k_gemm_mr() {
    extern __shared__ __align__(16) unsigned char dyn[];
    __half* As = (__half*)dyn;                       // [32][264]
    __half* Bs = (__half*)(dyn + MR_AS_BYTES);       // [256][168]
    float*  sa = (float*)(dyn + MR_AS_BYTES + MR_BS_BYTES);        // [40]
    float*  sc = (float*)(dyn + MR_AS_BYTES + MR_BS_BYTES + 160);  // [40]

    const int t = threadIdx.x;
    const int lane = t & 31;
    const int w = t >> 5;
    const int wr = w & 1;                  // row half (16 rows)
    const int wc = w >> 1;                 // 40-col quarter
    const int m0 = blockIdx.x * 32;
    const int i0 = m0 >> 3;                // 4 caps per block

    if (t < 40) sa[t] = 0.f;

    // load A: 32 rows x 256 halves = 1024 uint4, 4 per thread
    #pragma unroll
    for (int q = 0; q < 4; q++) {
        int e = t + q * 256;
        int r = e >> 5;
        int c16 = (e & 31) * 8;
        *(uint4*)(As + r * 264 + c16) =
            *(const uint4*)(g_xt + (size_t)(m0 + r) * BB + c16);
    }
    // load B: 256 rows x 40 uint2 = 10240, 40 per thread
    #pragma unroll
    for (int q = 0; q < 40; q++) {
        int e = t + q * 256;
        int r = e / 40;
        int c8 = e - r * 40;
        *(uint2*)(Bs + r * 168 + c8 * 4) =
            *(const uint2*)(g_vh + (size_t)r * JO + c8 * 4);
    }
    __syncthreads();

    float acc[5][4];
    #pragma unroll
    for (int n = 0; n < 5; n++) {
        #pragma unroll
        for (int q = 0; q < 4; q++) acc[n][q] = 0.f;
    }

    const unsigned int aaddr = smem_u32(As) +
        (unsigned int)(((wr * 16 + (lane & 15)) * 264 + (lane >> 4) * 8) * 2);
    const unsigned int baddr = smem_u32(Bs) +
        (unsigned int)(((lane & 15) * 168) * 2);

    #pragma unroll
    for (int kk = 0; kk < 16; kk++) {
        unsigned int a0, a1, a2, a3;
        ldsm_x4(a0, a1, a2, a3, aaddr + (unsigned int)(kk * 32));
        const unsigned int bk = baddr + (unsigned int)(kk * 16 * 336);
        #pragma unroll
        for (int nt = 0; nt < 5; nt++) {
            unsigned int b0, b1;
            ldsm_x2t(b0, b1, bk + (unsigned int)((wc * 40 + nt * 8) * 2));
            mma16816(acc[nt], a0, a1, a2, a3, b0, b1);
        }
    }

    // route epilogue: warp (wr,wc) holds rows r1 = m0+wr*16+g (cap wr*2) and
    // r1+8 (cap wr*2+1), cols wc*40+nt*8+c2 -> j = (wc*5+nt)>>1.
    const int g = lane >> 2;
    const int c2 = (lane & 3) * 2;
    const int r1 = m0 + wr * 16 + g;
    const int r2 = r1 + 8;
    float p0[5];
    float p1[5];
    #pragma unroll
    for (int n = 0; n < 5; n++) { p0[n] = 0.f; p1[n] = 0.f; }
    #pragma unroll
    for (int nt = 0; nt < 5; nt++) {
        int col = wc * 40 + nt * 8 + c2;
        __half2 w1 = *(const __half2*)(g_wt + (size_t)r1 * JO + col);
        __half2 w2 = *(const __half2*)(g_wt + (size_t)r2 * JO + col);
        float2 f1 = __half22float2(w1);
        float2 f2 = __half22float2(w2);
        p0[nt] += acc[nt][0] * f1.x + acc[nt][1] * f1.y;
        p1[nt] += acc[nt][2] * f2.x + acc[nt][3] * f2.y;
    }
    #pragma unroll
    for (int n = 0; n < 5; n++) {
        #pragma unroll
        for (int off = 16; off > 0; off >>= 1) {
            p0[n] += __shfl_xor_sync(0xffffffffu, p0[n], off);
            p1[n] += __shfl_xor_sync(0xffffffffu, p1[n], off);
        }
    }
    if (lane == 0) {
        #pragma unroll
        for (int n = 0; n < 5; n++) {
            int j = (wc * 5 + n) >> 1;
            atomicAdd(&sa[(wr * 2) * 10 + j], p0[n]);
            atomicAdd(&sa[(wr * 2 + 1) * 10 + j], p1[n]);
        }
    }
    __syncthreads();
    if (t < 4) {
        const int i = i0 + t;
        float bl[10];
        float ex[10];
        float mx = -1e30f;
        #pragma unroll
        for (int j = 0; j < 10; j++) {
            float nb = g_blog[i * 10 + j] + sa[t * 10 + j] * (1.0f / 256.0f);
            g_blog[i * 10 + j] = nb;
            bl[j] = nb;
            mx = fmaxf(mx, nb);
        }
        float sum = 0.f;
        #pragma unroll
        for (int j = 0; j < 10; j++) {
            ex[j] = expf(bl[j] - mx);
            sum += ex[j];
        }
        float inv = 1.f / sum;
        #pragma unroll
        for (int j = 0; j < 10; j++) {
            sc[t * 10 + j] = ex[j] * inv;
        }
    }
    __syncthreads();

    // write Wc = c * Wt for this block's 32 rows (next iteration's B).
    #pragma unroll
    for (int q = 0; q < 5; q++) {              // 32 rows x 40 uint2 = 1280
        int e = t + q * 256;
        int r = e / 40;
        int c8 = e - r * 40;
        int j = c8 >> 2;
        float cw = sc[(r >> 3) * 10 + j];
        uint2 raw = *(const uint2*)(g_wt + (size_t)(m0 + r) * JO + c8 * 4);
        __half2 h0 = *(__half2*)&raw.x;
        __half2 h1 = *(__half2*)&raw.y;
        float2 f0 = __half22float2(h0);
        float2 f1 = __half22float2(h1);
        __half2 o0 = __floats2half2_rn(cw * f0.x, cw * f0.y);
        __half2 o1 = __floats2half2_rn(cw * f1.x, cw * f1.y);
        uint2 outv;
        outv.x = *(unsigned int*)&o0;
        outv.y = *(unsigned int*)&o1;
        *(uint2*)(g_wc + (size_t)(m0 + r) * JO + c8 * 4) = outv;
    }
}

extern "C" void kernel_launch(void* const* d_in, const int* in_sizes, int n_in,
                              void* d_out, int out_size) {
    const float* x = (const float*)d_in[0];
    const float* w = (const float*)d_in[1];
    if (n_in >= 2 && in_sizes[0] == NIN * NOUT * DOUT * DIN
                  && in_sizes[1] == BB * DIN * NIN) {
        const float* tmp = x;
        x = w;
        w = tmp;
    }
    float* out = (float*)d_out;

    cudaFuncSetAttribute(k_gemm_mr,
                         cudaFuncAttributeMaxDynamicSharedMemorySize,
                         MR_SMEM_BYTES);

    k_prep<<<3456, 256>>>(x, w);

    k_gemm_s<<<dim3(KSPLIT, 4), 256>>>();
    k_squash<<<BB, 160>>>((float*)0);
    k_gemm_mr<<<KD / 32, 256, MR_SMEM_BYTES>>>();

    k_gemm_s<<<dim3(KSPLIT, 4), 256>>>();
    k_squash<<<BB, 160>>>((float*)0);
    k_gemm_mr<<<KD / 32, 256, MR_SMEM_BYTES>>>();

    k_gemm_s<<<dim3(KSPLIT, 4), 256>>>();
    k_squash<<<BB, 160>>>(out);
}